// round 4
// baseline (speedup 1.0000x reference)
#include <cuda_runtime.h>

#define BATCH     16384
#define QSEQ      1204
#define FDIM      7
#define NQUAD     301
#define NCHUNKS   120
#define NOFF      5
#define WINSZ     10
#define NCAT      600
#define H1DIM     128
#define H2DIM     32
#define ODIM      2

// Scratch: cat stored k-major: g_cat[k*BATCH + b]
__device__ float g_cat[(size_t)NCAT * BATCH];

// ---------------------------------------------------------------------------
// f32x2 packed FFMA helpers
// ---------------------------------------------------------------------------
__device__ __forceinline__ unsigned long long pack2(float lo, float hi) {
    unsigned long long r;
    asm("mov.b64 %0, {%1, %2};" : "=l"(r) : "f"(lo), "f"(hi));
    return r;
}
__device__ __forceinline__ void unpack2(unsigned long long v, float& lo, float& hi) {
    asm("mov.b64 {%0, %1}, %2;" : "=f"(lo), "=f"(hi) : "l"(v));
}
__device__ __forceinline__ unsigned long long ffma2(unsigned long long a,
                                                    unsigned long long b,
                                                    unsigned long long c) {
    unsigned long long d;
    asm("fma.rn.f32x2 %0, %1, %2, %3;" : "=l"(d) : "l"(a), "l"(b), "l"(c));
    return d;
}

__device__ __forceinline__ void cp_async16(void* smem_dst, const void* gsrc) {
    unsigned s = (unsigned)__cvta_generic_to_shared(smem_dst);
    asm volatile("cp.async.ca.shared.global [%0], [%1], 16;\n" :: "r"(s), "l"(gsrc));
}
__device__ __forceinline__ void cp_commit() {
    asm volatile("cp.async.commit_group;\n" ::: "memory");
}
__device__ __forceinline__ void cp_wait0() {
    asm volatile("cp.async.wait_group 0;\n" ::: "memory");
}

// ===========================================================================
// Kernel 1: dot-7 + windowed max pool (DRAM streaming)
// ===========================================================================
#define K1_ROWS 8
__global__ __launch_bounds__(256)
void pool_kernel(const float* __restrict__ x,
                 const float* __restrict__ w_step,
                 const float* __restrict__ b_step)
{
    __shared__ float sm_out[K1_ROWS][QSEQ];

    const int tid = threadIdx.x;
    const size_t b0 = (size_t)blockIdx.x * K1_ROWS;

    float ws[FDIM];
#pragma unroll
    for (int f = 0; f < FDIM; ++f) ws[f] = __ldg(&w_step[f]);
    const float bs = __ldg(b_step);

    for (int it = tid; it < K1_ROWS * NQUAD; it += 256) {
        const int r  = it / NQUAD;
        const int qd = it - r * NQUAD;
        const float4* p = (const float4*)(x + (b0 + (size_t)r) * (QSEQ * FDIM) + qd * 28);
        float v[28];
#pragma unroll
        for (int i = 0; i < 7; ++i) {
            float4 t = p[i];
            v[i*4+0] = t.x; v[i*4+1] = t.y; v[i*4+2] = t.z; v[i*4+3] = t.w;
        }
#pragma unroll
        for (int qq = 0; qq < 4; ++qq) {
            float acc = bs;
#pragma unroll
            for (int f = 0; f < FDIM; ++f)
                acc = fmaf(v[qq*FDIM + f], ws[f], acc);
            sm_out[r][qd*4 + qq] = acc;
        }
    }
    __syncthreads();

    for (int it = tid; it < K1_ROWS * NCHUNKS; it += 256) {
        const int r = it & (K1_ROWS - 1);
        const int i = it >> 3;
        const float* o = &sm_out[r][i * WINSZ];
        float v[14];
#pragma unroll
        for (int j = 0; j < 14; ++j) v[j] = o[j];

        float common = v[4];
#pragma unroll
        for (int j = 5; j < 10; ++j) common = fmaxf(common, v[j]);
        const float P1 = v[10];
        const float P2 = fmaxf(P1, v[11]);
        const float P3 = fmaxf(P2, v[12]);
        const float P4 = fmaxf(P3, v[13]);
        const float T3 = v[3];
        const float T2 = fmaxf(v[2], T3);
        const float T1 = fmaxf(v[1], T2);
        const float T0 = fmaxf(v[0], T1);

        const size_t base = b0 + (size_t)r;
        const size_t c0 = (size_t)(i * NOFF) * BATCH;
        g_cat[c0 + 0*BATCH + base] = fmaxf(common, T0);
        g_cat[c0 + 1*BATCH + base] = fmaxf(fmaxf(common, T1), P1);
        g_cat[c0 + 2*BATCH + base] = fmaxf(fmaxf(common, T2), P2);
        g_cat[c0 + 3*BATCH + base] = fmaxf(fmaxf(common, T3), P3);
        g_cat[c0 + 4*BATCH + base] = fmaxf(common, P4);
    }
}

// ===========================================================================
// Kernel 2: MLP — 32 rows/CTA, barrier-free layer A, wA via LDG.128 (L1-hot)
// Thread = (neuron quad jq=tid&31, row quad rs=tid>>5). 512 CTAs x 256 thr.
// ===========================================================================
#define NROWS  32

// dyn smem (floats):
//   sm_cat : [0, 19200)   cat[k][32]   (h1[128][32]=4096 aliases after layer A)
//   sm_h2  : [19200, 20224)  h2[32 rows][32]
#define SM_F     (NCAT * NROWS + NROWS * H2DIM)
#define SM_BYTES (SM_F * 4)

__global__ __launch_bounds__(256)
void mlp_kernel(const float* __restrict__ wA,
                const float* __restrict__ bA,
                const float* __restrict__ wB,
                const float* __restrict__ bB,
                const float* __restrict__ wC,
                const float* __restrict__ bC,
                float* __restrict__ out)
{
    extern __shared__ float smem[];
    float* sm_cat = smem;                    // 19200
    float* sm_h1  = smem;                    // 4096, alias after layer A
    float* sm_h2  = smem + NCAT * NROWS;     // 1024

    const int tid = threadIdx.x;
    const size_t b0 = (size_t)blockIdx.x * NROWS;

    // ---- load cat tile: 600 k x 32 rows, coalesced float4 via cp.async ----
    for (int idx = tid; idx < NCAT * NROWS / 4; idx += 256) {
        const int k  = idx >> 3;
        const int r4 = idx & 7;
        cp_async16(&sm_cat[k * NROWS + r4 * 4],
                   &g_cat[(size_t)k * BATCH + b0 + r4 * 4]);
    }
    cp_commit();
    cp_wait0();
    __syncthreads();

    // ---- Layer A: barrier-free. 8 f32x2 accumulators (2 neuron-pairs x 4 rows)
    const int jq = tid & 31;          // neuron quad -> j0 = 4*jq
    const int rs = tid >> 5;          // row quad    -> r0 = 4*rs
    const float* wAp = wA + jq * 4;
    const float* cb  = sm_cat + rs * 4;

    unsigned long long a00 = 0, a01 = 0, a02 = 0, a03 = 0;  // neurons (j0,j0+1) x rows 0..3
    unsigned long long a10 = 0, a11 = 0, a12 = 0, a13 = 0;  // neurons (j0+2,j0+3) x rows 0..3

#pragma unroll 4
    for (int k = 0; k < NCAT; ++k) {
        const ulonglong2 w2 = *(const ulonglong2*)(wAp + k * H1DIM);  // LDG.128
        const float4 c = *(const float4*)(cb + k * NROWS);            // LDS.128 bcast
        const unsigned long long cx = pack2(c.x, c.x);
        const unsigned long long cy = pack2(c.y, c.y);
        const unsigned long long cz = pack2(c.z, c.z);
        const unsigned long long cw = pack2(c.w, c.w);
        a00 = ffma2(w2.x, cx, a00);
        a10 = ffma2(w2.y, cx, a10);
        a01 = ffma2(w2.x, cy, a01);
        a11 = ffma2(w2.y, cy, a11);
        a02 = ffma2(w2.x, cz, a02);
        a12 = ffma2(w2.y, cz, a12);
        a03 = ffma2(w2.x, cw, a03);
        a13 = ffma2(w2.y, cw, a13);
    }

    const float4 b4 = *(const float4*)&bA[jq * 4];
    __syncthreads();    // all cat reads complete; safe to overwrite with h1

    // epilogue: h1[j][r] = relu(acc + bias), layout h1[j*32 + r]
    {
        const int j0 = jq * 4;
        const int r0 = rs * 4;
        float lo, hi;
        unsigned long long accs[8] = {a00, a01, a02, a03, a10, a11, a12, a13};
#pragma unroll
        for (int p = 0; p < 2; ++p) {
            const float bl = p ? b4.z : b4.x;
            const float bh = p ? b4.w : b4.y;
#pragma unroll
            for (int r = 0; r < 4; ++r) {
                unpack2(accs[p * 4 + r], lo, hi);
                sm_h1[(j0 + 2*p + 0) * NROWS + r0 + r] = fmaxf(lo + bl, 0.0f);
                sm_h1[(j0 + 2*p + 1) * NROWS + r0 + r] = fmaxf(hi + bh, 0.0f);
            }
        }
    }
    __syncthreads();

    // ---- Layer B: h2[r][m] = relu(sum_j h1[j][r] * wB[j][m] + bB[m]) ----
    {
        const int m  = tid & 31;
        const int r0 = (tid >> 5) * 4;
        float s0 = 0, s1 = 0, s2 = 0, s3 = 0;
#pragma unroll 4
        for (int j = 0; j < H1DIM; ++j) {
            const float wb = __ldg(&wB[j * H2DIM + m]);
            const float4 h = *(const float4*)&sm_h1[j * NROWS + r0];
            s0 = fmaf(h.x, wb, s0);
            s1 = fmaf(h.y, wb, s1);
            s2 = fmaf(h.z, wb, s2);
            s3 = fmaf(h.w, wb, s3);
        }
        const float bm = __ldg(&bB[m]);
        sm_h2[(r0 + 0) * H2DIM + m] = fmaxf(s0 + bm, 0.0f);
        sm_h2[(r0 + 1) * H2DIM + m] = fmaxf(s1 + bm, 0.0f);
        sm_h2[(r0 + 2) * H2DIM + m] = fmaxf(s2 + bm, 0.0f);
        sm_h2[(r0 + 3) * H2DIM + m] = fmaxf(s3 + bm, 0.0f);
    }
    __syncthreads();

    // ---- Layer C ----
    if (tid < NROWS * ODIM) {
        const int r = tid >> 1;
        const int c = tid & 1;
        float acc = __ldg(&bC[c]);
#pragma unroll
        for (int m = 0; m < H2DIM; ++m)
            acc = fmaf(sm_h2[r * H2DIM + m], __ldg(&wC[m * ODIM + c]), acc);
        out[(b0 + (size_t)r) * ODIM + c] = acc;
    }
}

extern "C" void kernel_launch(void* const* d_in, const int* in_sizes, int n_in,
                              void* d_out, int out_size)
{
    const float* x      = (const float*)d_in[0];
    const float* w_step = (const float*)d_in[1];
    const float* b_step = (const float*)d_in[2];
    const float* wA     = (const float*)d_in[3];
    const float* bA     = (const float*)d_in[4];
    const float* wB     = (const float*)d_in[5];
    const float* bB     = (const float*)d_in[6];
    const float* wC     = (const float*)d_in[7];
    const float* bC     = (const float*)d_in[8];
    float* out          = (float*)d_out;

    cudaFuncSetAttribute(mlp_kernel, cudaFuncAttributeMaxDynamicSharedMemorySize, SM_BYTES);

    pool_kernel<<<BATCH / K1_ROWS, 256>>>(x, w_step, b_step);
    mlp_kernel<<<BATCH / NROWS, 256, SM_BYTES>>>(wA, bA, wB, bB, wC, bC, out);
}

// round 5
// speedup vs baseline: 2.0873x; 2.0873x over previous
#include <cuda_runtime.h>

#define BATCH     16384
#define QSEQ      1204
#define FDIM      7
#define NQUAD     301
#define NCHUNKS   120
#define NOFF      5
#define WINSZ     10
#define NCAT      600
#define H1DIM     128
#define H2DIM     32
#define ODIM      2

// Scratch: cat stored k-major: g_cat[k*BATCH + b]
__device__ float g_cat[(size_t)NCAT * BATCH];

// ---------------------------------------------------------------------------
// f32x2 packed FFMA helpers
// ---------------------------------------------------------------------------
__device__ __forceinline__ unsigned long long pack2(float lo, float hi) {
    unsigned long long r;
    asm("mov.b64 %0, {%1, %2};" : "=l"(r) : "f"(lo), "f"(hi));
    return r;
}
__device__ __forceinline__ void unpack2(unsigned long long v, float& lo, float& hi) {
    asm("mov.b64 {%0, %1}, %2;" : "=f"(lo), "=f"(hi) : "l"(v));
}
__device__ __forceinline__ unsigned long long ffma2(unsigned long long a,
                                                    unsigned long long b,
                                                    unsigned long long c) {
    unsigned long long d;
    asm("fma.rn.f32x2 %0, %1, %2, %3;" : "=l"(d) : "l"(a), "l"(b), "l"(c));
    return d;
}

__device__ __forceinline__ void cp_async16(void* smem_dst, const void* gsrc) {
    unsigned s = (unsigned)__cvta_generic_to_shared(smem_dst);
    asm volatile("cp.async.ca.shared.global [%0], [%1], 16;\n" :: "r"(s), "l"(gsrc));
}
__device__ __forceinline__ void cp_commit() {
    asm volatile("cp.async.commit_group;\n" ::: "memory");
}
__device__ __forceinline__ void cp_wait0() {
    asm volatile("cp.async.wait_group 0;\n" ::: "memory");
}

// ===========================================================================
// Kernel 1: dot-7 + windowed max pool (DRAM streaming)  — unchanged (known good)
// ===========================================================================
#define K1_ROWS 8
__global__ __launch_bounds__(256)
void pool_kernel(const float* __restrict__ x,
                 const float* __restrict__ w_step,
                 const float* __restrict__ b_step)
{
    __shared__ float sm_out[K1_ROWS][QSEQ];

    const int tid = threadIdx.x;
    const size_t b0 = (size_t)blockIdx.x * K1_ROWS;

    float ws[FDIM];
#pragma unroll
    for (int f = 0; f < FDIM; ++f) ws[f] = __ldg(&w_step[f]);
    const float bs = __ldg(b_step);

    for (int it = tid; it < K1_ROWS * NQUAD; it += 256) {
        const int r  = it / NQUAD;
        const int qd = it - r * NQUAD;
        const float4* p = (const float4*)(x + (b0 + (size_t)r) * (QSEQ * FDIM) + qd * 28);
        float v[28];
#pragma unroll
        for (int i = 0; i < 7; ++i) {
            float4 t = p[i];
            v[i*4+0] = t.x; v[i*4+1] = t.y; v[i*4+2] = t.z; v[i*4+3] = t.w;
        }
#pragma unroll
        for (int qq = 0; qq < 4; ++qq) {
            float acc = bs;
#pragma unroll
            for (int f = 0; f < FDIM; ++f)
                acc = fmaf(v[qq*FDIM + f], ws[f], acc);
            sm_out[r][qd*4 + qq] = acc;
        }
    }
    __syncthreads();

    for (int it = tid; it < K1_ROWS * NCHUNKS; it += 256) {
        const int r = it & (K1_ROWS - 1);
        const int i = it >> 3;
        const float* o = &sm_out[r][i * WINSZ];
        float v[14];
#pragma unroll
        for (int j = 0; j < 14; ++j) v[j] = o[j];

        float common = v[4];
#pragma unroll
        for (int j = 5; j < 10; ++j) common = fmaxf(common, v[j]);
        const float P1 = v[10];
        const float P2 = fmaxf(P1, v[11]);
        const float P3 = fmaxf(P2, v[12]);
        const float P4 = fmaxf(P3, v[13]);
        const float T3 = v[3];
        const float T2 = fmaxf(v[2], T3);
        const float T1 = fmaxf(v[1], T2);
        const float T0 = fmaxf(v[0], T1);

        const size_t base = b0 + (size_t)r;
        const size_t c0 = (size_t)(i * NOFF) * BATCH;
        g_cat[c0 + 0*BATCH + base] = fmaxf(common, T0);
        g_cat[c0 + 1*BATCH + base] = fmaxf(fmaxf(common, T1), P1);
        g_cat[c0 + 2*BATCH + base] = fmaxf(fmaxf(common, T2), P2);
        g_cat[c0 + 3*BATCH + base] = fmaxf(fmaxf(common, T3), P3);
        g_cat[c0 + 4*BATCH + base] = fmaxf(common, P4);
    }
}

// ===========================================================================
// Kernel 2: MLP — 32 rows/CTA, cp.async double-buffered wA tiles (KT=24),
//           1 sync per tile, 8 FFMA2 per k from 2 LDS.128.
// ===========================================================================
#define NROWS  32
#define KT     24
#define NTILE  25                   // 25 * 24 = 600
#define TILE_F (KT * H1DIM)         // 3072 floats = 768 float4 (3 per thread)

// dyn smem (floats):
//   sm_cat : [0, 19200)                cat[k][32]  (h1[128][32] aliases after A)
//   sm_wA  : [19200, 19200+3072) and [22272, 25344)
//   sm_h2  : [25344, 26368)
#define SM_F     (NCAT * NROWS + 2 * TILE_F + NROWS * H2DIM)
#define SM_BYTES (SM_F * 4)

__global__ __launch_bounds__(256)
void mlp_kernel(const float* __restrict__ wA,
                const float* __restrict__ bA,
                const float* __restrict__ wB,
                const float* __restrict__ bB,
                const float* __restrict__ wC,
                const float* __restrict__ bC,
                float* __restrict__ out)
{
    extern __shared__ float smem[];
    float* sm_cat = smem;                         // 19200
    float* sm_h1  = smem;                         // 4096 alias after layer A
    float* sm_wAb0 = smem + NCAT * NROWS;         // 3072
    float* sm_wAb1 = sm_wAb0 + TILE_F;            // 3072
    float* sm_h2  = sm_wAb1 + TILE_F;             // 1024

    const int tid = threadIdx.x;
    const size_t b0 = (size_t)blockIdx.x * NROWS;

    // ---- prologue: cat tile (group) then wA tile 0 (group) ----
    for (int idx = tid; idx < NCAT * NROWS / 4; idx += 256) {
        const int k  = idx >> 3;
        const int r4 = idx & 7;
        cp_async16(&sm_cat[k * NROWS + r4 * 4],
                   &g_cat[(size_t)k * BATCH + b0 + r4 * 4]);
    }
    cp_commit();
#pragma unroll
    for (int i = 0; i < 3; ++i)
        cp_async16(sm_wAb0 + (tid + i * 256) * 4, wA + (tid + i * 256) * 4);
    cp_commit();

    // ---- Layer A over 25 k-tiles, double buffered, 1 sync/tile ----
    const int jq = tid & 31;            // j0 = 4*jq
    const int rs = tid >> 5;            // r0 = 4*rs
    const int j0 = jq * 4;
    const int r0 = rs * 4;

    // acc[n][p]: neuron j0+n, row pair (r0+2p, r0+2p+1)
    unsigned long long acc[4][2];
#pragma unroll
    for (int n = 0; n < 4; ++n) { acc[n][0] = 0ULL; acc[n][1] = 0ULL; }

    for (int t = 0; t < NTILE; ++t) {
        cp_wait0();          // tile t (and cat on t==0) has landed for this thread
        __syncthreads();     // all threads' data landed; prev buffer fully consumed
        if (t + 1 < NTILE) {
            float* dst = ((t + 1) & 1) ? sm_wAb1 : sm_wAb0;
            const float* src = wA + (size_t)(t + 1) * TILE_F;
#pragma unroll
            for (int i = 0; i < 3; ++i)
                cp_async16(dst + (tid + i * 256) * 4, src + (tid + i * 256) * 4);
            cp_commit();
        }

        const float* wt = (t & 1) ? sm_wAb1 : sm_wAb0;
        const float* cb = sm_cat + (t * KT) * NROWS + r0;
#pragma unroll 4
        for (int kk = 0; kk < KT; ++kk) {
            const float4 w4 = *(const float4*)(wt + kk * H1DIM + j0);      // LDS.128
            const ulonglong2 c2 = *(const ulonglong2*)(cb + kk * NROWS);   // LDS.128 bcast
            const unsigned long long pw0 = pack2(w4.x, w4.x);
            const unsigned long long pw1 = pack2(w4.y, w4.y);
            const unsigned long long pw2 = pack2(w4.z, w4.z);
            const unsigned long long pw3 = pack2(w4.w, w4.w);
            acc[0][0] = ffma2(c2.x, pw0, acc[0][0]);
            acc[1][0] = ffma2(c2.x, pw1, acc[1][0]);
            acc[2][0] = ffma2(c2.x, pw2, acc[2][0]);
            acc[3][0] = ffma2(c2.x, pw3, acc[3][0]);
            acc[0][1] = ffma2(c2.y, pw0, acc[0][1]);
            acc[1][1] = ffma2(c2.y, pw1, acc[1][1]);
            acc[2][1] = ffma2(c2.y, pw2, acc[2][1]);
            acc[3][1] = ffma2(c2.y, pw3, acc[3][1]);
        }
    }

    const float4 b4 = *(const float4*)&bA[j0];
    __syncthreads();     // all cat reads done; safe to overwrite with h1

    // epilogue: h1[j][r] = relu(acc + bias), layout h1[j*32 + r]
    {
        float lo, hi;
        const float bb[4] = {b4.x, b4.y, b4.z, b4.w};
#pragma unroll
        for (int n = 0; n < 4; ++n) {
#pragma unroll
            for (int p = 0; p < 2; ++p) {
                unpack2(acc[n][p], lo, hi);
                sm_h1[(j0 + n) * NROWS + r0 + 2*p + 0] = fmaxf(lo + bb[n], 0.0f);
                sm_h1[(j0 + n) * NROWS + r0 + 2*p + 1] = fmaxf(hi + bb[n], 0.0f);
            }
        }
    }
    __syncthreads();

    // ---- Layer B: h2[r][m] = relu(sum_j h1[j][r] * wB[j][m] + bB[m]) ----
    {
        const int m  = tid & 31;
        const int rb = (tid >> 5) * 4;
        float s0 = 0, s1 = 0, s2 = 0, s3 = 0;
#pragma unroll 4
        for (int j = 0; j < H1DIM; ++j) {
            const float wb = __ldg(&wB[j * H2DIM + m]);
            const float4 h = *(const float4*)&sm_h1[j * NROWS + rb];
            s0 = fmaf(h.x, wb, s0);
            s1 = fmaf(h.y, wb, s1);
            s2 = fmaf(h.z, wb, s2);
            s3 = fmaf(h.w, wb, s3);
        }
        const float bm = __ldg(&bB[m]);
        sm_h2[(rb + 0) * H2DIM + m] = fmaxf(s0 + bm, 0.0f);
        sm_h2[(rb + 1) * H2DIM + m] = fmaxf(s1 + bm, 0.0f);
        sm_h2[(rb + 2) * H2DIM + m] = fmaxf(s2 + bm, 0.0f);
        sm_h2[(rb + 3) * H2DIM + m] = fmaxf(s3 + bm, 0.0f);
    }
    __syncthreads();

    // ---- Layer C ----
    if (tid < NROWS * ODIM) {
        const int r = tid >> 1;
        const int c = tid & 1;
        float s = __ldg(&bC[c]);
#pragma unroll
        for (int m = 0; m < H2DIM; ++m)
            s = fmaf(sm_h2[r * H2DIM + m], __ldg(&wC[m * ODIM + c]), s);
        out[(b0 + (size_t)r) * ODIM + c] = s;
    }
}

extern "C" void kernel_launch(void* const* d_in, const int* in_sizes, int n_in,
                              void* d_out, int out_size)
{
    const float* x      = (const float*)d_in[0];
    const float* w_step = (const float*)d_in[1];
    const float* b_step = (const float*)d_in[2];
    const float* wA     = (const float*)d_in[3];
    const float* bA     = (const float*)d_in[4];
    const float* wB     = (const float*)d_in[5];
    const float* bB     = (const float*)d_in[6];
    const float* wC     = (const float*)d_in[7];
    const float* bC     = (const float*)d_in[8];
    float* out          = (float*)d_out;

    cudaFuncSetAttribute(mlp_kernel, cudaFuncAttributeMaxDynamicSharedMemorySize, SM_BYTES);

    pool_kernel<<<BATCH / K1_ROWS, 256>>>(x, w_step, b_step);
    mlp_kernel<<<BATCH / NROWS, 256, SM_BYTES>>>(wA, bA, wB, bB, wC, bC, out);
}